// round 3
// baseline (speedup 1.0000x reference)
#include <cuda_runtime.h>

#define NUM_NODES 1000000
#define NUM_EDGES 16000000
#define F  6
#define FP 8   // padded feature width (32 B row = one L2 sector; 16B-aligned v4 atomics)

// Scratch: device globals (no allocation allowed anywhere).
__device__ __align__(128) float g_x8 [NUM_NODES * FP];  // padded copy of x
__device__ __align__(128) float g_agg[NUM_NODES * FP];  // scatter-add accumulator
__device__ __align__(128) float g_h8 [NUM_NODES * FP];  // padded layer-1 output
__device__ int g_idx_is32;                              // 1 if edge_index is int32

// ---------------------------------------------------------------------------
// Kernel 0: detect edge-index dtype. int64 indices < 1M always have zero high
// words; int32 data read as int64 fuses two indices -> huge values.
// Deterministic, runs every launch.
// ---------------------------------------------------------------------------
__global__ void detect_kernel(const long long* __restrict__ ei) {
    __shared__ int bad;
    if (threadIdx.x == 0) bad = 0;
    __syncthreads();
    #pragma unroll
    for (int r = 0; r < 16; r++) {
        long long v = ei[threadIdx.x + r * 256];
        if ((unsigned long long)v >= (unsigned long long)NUM_NODES) bad = 1;
    }
    __syncthreads();
    if (threadIdx.x == 0) g_idx_is32 = bad;
}

// ---------------------------------------------------------------------------
// Kernel 1: pad x into g_x8 (zeros in lanes 6,7) and zero g_agg.
// ---------------------------------------------------------------------------
__global__ void prep_kernel(const float* __restrict__ x) {
    int i = blockIdx.x * blockDim.x + threadIdx.x;
    if (i >= NUM_NODES) return;
    const float* xr = x + (size_t)i * F;
    float4 lo = make_float4(xr[0], xr[1], xr[2], xr[3]);
    float4 hi = make_float4(xr[4], xr[5], 0.f, 0.f);
    float4* px = reinterpret_cast<float4*>(g_x8 + (size_t)i * FP);
    px[0] = lo; px[1] = hi;
    float4 z = make_float4(0.f, 0.f, 0.f, 0.f);
    float4* pa = reinterpret_cast<float4*>(g_agg + (size_t)i * FP);
    pa[0] = z; pa[1] = z;
}

// 16-byte vector reduction atomic (sm_90+): 2 LTS ops per edge instead of 6.
__device__ __forceinline__ void red_add_v4(float* p, float4 v) {
    asm volatile("red.global.add.v4.f32 [%0], {%1, %2, %3, %4};"
                 :: "l"(p), "f"(v.x), "f"(v.y), "f"(v.z), "f"(v.w)
                 : "memory");
}

__device__ __forceinline__ void do_edge(const float* __restrict__ feat,
                                        unsigned s, unsigned d) {
    if (s >= NUM_NODES || d >= NUM_NODES) return;   // safety: no IMA possible
    const float4* f = reinterpret_cast<const float4*>(feat + (size_t)s * FP);
    float4 lo = f[0];
    float4 hi = f[1];                // lanes 6,7 zero -> harmless adds
    float* a = g_agg + (size_t)d * FP;
    red_add_v4(a,     lo);
    red_add_v4(a + 4, hi);
}

// ---------------------------------------------------------------------------
// Kernel 2/4: edge scatter. agg[dst] += feat[src]. 2 edges per thread.
// Dtype path chosen by g_idx_is32 (uniform branch, flag is L2-broadcast).
// ---------------------------------------------------------------------------
template <int PHASE>
__global__ void scatter_kernel(const void* __restrict__ ei) {
    int i = blockIdx.x * blockDim.x + threadIdx.x;
    if (i >= NUM_EDGES / 2) return;
    const float* feat = (PHASE == 0) ? g_x8 : g_h8;

    if (g_idx_is32) {
        const int* src = (const int*)ei;
        const int* dst = src + NUM_EDGES;
        int2 s2 = reinterpret_cast<const int2*>(src)[i];
        int2 d2 = reinterpret_cast<const int2*>(dst)[i];
        do_edge(feat, (unsigned)s2.x, (unsigned)d2.x);
        do_edge(feat, (unsigned)s2.y, (unsigned)d2.y);
    } else {
        const long long* src = (const long long*)ei;
        const long long* dst = src + NUM_EDGES;
        longlong2 s2 = reinterpret_cast<const longlong2*>(src)[i];
        longlong2 d2 = reinterpret_cast<const longlong2*>(dst)[i];
        do_edge(feat, (unsigned)s2.x, (unsigned)d2.x);
        do_edge(feat, (unsigned)s2.y, (unsigned)d2.y);
    }
}

// ---------------------------------------------------------------------------
// Kernel 3/5: per-node dense transform.
//   h[k] = b[k] + sum_j agg[j]*W_rel[k][j] + sum_j in[j]*W_root[k][j]
// FINAL=false : write padded h into g_h8, re-zero g_agg for layer 2.
// FINAL=true  : argmax (first-max wins, matches jnp.argmax) -> one-hot.
// ---------------------------------------------------------------------------
template <bool FINAL>
__global__ void transform_kernel(const float* __restrict__ Wrel,
                                 const float* __restrict__ Wroot,
                                 const float* __restrict__ b,
                                 float* __restrict__ out) {
    __shared__ float swr[36], swo[36], sb[6];
    int t = threadIdx.x;
    if (t < 36)        swr[t]      = Wrel[t];
    else if (t < 72)   swo[t - 36] = Wroot[t - 36];
    else if (t < 78)   sb[t - 72]  = b[t - 72];
    __syncthreads();

    int i = blockIdx.x * blockDim.x + t;
    if (i >= NUM_NODES) return;

    const float* in_feat = FINAL ? g_h8 : g_x8;

    const float4* pa = reinterpret_cast<const float4*>(g_agg + (size_t)i * FP);
    float4 a0 = pa[0], a1 = pa[1];
    const float4* px = reinterpret_cast<const float4*>(in_feat + (size_t)i * FP);
    float4 x0 = px[0], x1 = px[1];

    float ag[6] = {a0.x, a0.y, a0.z, a0.w, a1.x, a1.y};
    float xv[6] = {x0.x, x0.y, x0.z, x0.w, x1.x, x1.y};

    float h[6];
    #pragma unroll
    for (int k = 0; k < 6; k++) {
        float acc = sb[k];
        #pragma unroll
        for (int j = 0; j < 6; j++) {
            acc = fmaf(ag[j], swr[k * 6 + j], acc);
            acc = fmaf(xv[j], swo[k * 6 + j], acc);
        }
        h[k] = acc;
    }

    if (!FINAL) {
        float4 z = make_float4(0.f, 0.f, 0.f, 0.f);
        float4* paw = reinterpret_cast<float4*>(g_agg + (size_t)i * FP);
        paw[0] = z; paw[1] = z;
        float4* ph = reinterpret_cast<float4*>(g_h8 + (size_t)i * FP);
        ph[0] = make_float4(h[0], h[1], h[2], h[3]);
        ph[1] = make_float4(h[4], h[5], 0.f, 0.f);
    } else {
        int best = 0; float bv = h[0];
        #pragma unroll
        for (int k = 1; k < 6; k++)
            if (h[k] > bv) { bv = h[k]; best = k; }
        float* po = out + (size_t)i * F;
        #pragma unroll
        for (int k = 0; k < 6; k++)
            po[k] = (k == best) ? 1.f : 0.f;
    }
}

extern "C" void kernel_launch(void* const* d_in, const int* in_sizes, int n_in,
                              void* d_out, int out_size) {
    const float* x      = (const float*)d_in[0];
    const void*  ei     = d_in[1];               // int32 or int64: detected on device
    const float* Wrel1  = (const float*)d_in[2];
    const float* Wroot1 = (const float*)d_in[3];
    const float* b1     = (const float*)d_in[4];
    const float* Wrel2  = (const float*)d_in[5];
    const float* Wroot2 = (const float*)d_in[6];
    const float* b2     = (const float*)d_in[7];
    float*       out    = (float*)d_out;

    const int BLK = 256;
    const int node_grid = (NUM_NODES + BLK - 1) / BLK;
    const int edge_grid = (NUM_EDGES / 2 + BLK - 1) / BLK;

    detect_kernel<<<1, 256>>>((const long long*)ei);
    // Layer 1
    prep_kernel<<<node_grid, BLK>>>(x);
    scatter_kernel<0><<<edge_grid, BLK>>>(ei);
    transform_kernel<false><<<node_grid, BLK>>>(Wrel1, Wroot1, b1, nullptr);
    // Layer 2
    scatter_kernel<1><<<edge_grid, BLK>>>(ei);
    transform_kernel<true><<<node_grid, BLK>>>(Wrel2, Wroot2, b2, out);
}